// round 1
// baseline (speedup 1.0000x reference)
#include <cuda_runtime.h>

#define T_STEPS 10
#define B_SZ    32
#define CIN     3
#define COUT    64
#define SPAT    4096            // 64*64
#define N_THR   (T_STEPS * COUT)
#define DECAY   0.2f
#define INH     1.625f

// Scratch: conv results for all timesteps, in output layout (t,b,c,h,w).
__device__ float    g_i[T_STEPS * B_SZ * COUT * SPAT];   // 335.5 MB
__device__ unsigned g_thr_keys[N_THR];
__device__ float4   g_thrv[N_THR];                       // {thr, 0.4*thr, 8/thr, INH*thr}

// ---------------------------------------------------------------------------
__global__ void init_keys() {
    int i = blockIdx.x * blockDim.x + threadIdx.x;
    if (i < N_THR) g_thr_keys[i] = 0u;   // key 0 == very negative float
}

// ---------------------------------------------------------------------------
// Conv 3x3, stride 1, pad 1. Block = 32x8 pixel tile for one (t,b); loops all
// 64 output channels. Also produces per-(t,c) global max via ordered-int keys.
__global__ void __launch_bounds__(256) conv_kernel(const float* __restrict__ x,
                                                   const float* __restrict__ Wt) {
    __shared__ float    xs[CIN][10][34];
    __shared__ float    ws[COUT * 28];       // 27 weights + 1 pad per channel (112B rows, 16B aligned)
    __shared__ unsigned smax[COUT];

    const int tb  = blockIdx.z;              // t*B + b
    const int t   = tb >> 5;
    const int tid = threadIdx.y * 32 + threadIdx.x;

    for (int idx = tid; idx < COUT * 27; idx += 256) {
        int co = idx / 27;
        ws[co * 28 + (idx - co * 27)] = Wt[idx];
    }
    if (tid < COUT) { ws[tid * 28 + 27] = 0.f; smax[tid] = 0u; }

    const float* xb = x + tb * (CIN * SPAT);
    const int y0 = blockIdx.y * 8;
    const int x0 = blockIdx.x * 32;
    for (int idx = tid; idx < CIN * 340; idx += 256) {
        int ci  = idx / 340;
        int rem = idx - ci * 340;
        int yy  = rem / 34;
        int xx  = rem - yy * 34;
        int gy = y0 + yy - 1, gx = x0 + xx - 1;
        float v = 0.f;
        if ((unsigned)gy < 64u && (unsigned)gx < 64u) v = xb[ci * SPAT + gy * 64 + gx];
        xs[ci][yy][xx] = v;
    }
    __syncthreads();

    const int px = threadIdx.x, py = threadIdx.y;
    float r[27];
#pragma unroll
    for (int ci = 0; ci < 3; ci++)
#pragma unroll
        for (int ky = 0; ky < 3; ky++)
#pragma unroll
            for (int kx = 0; kx < 3; kx++)
                r[ci * 9 + ky * 3 + kx] = xs[ci][py + ky][px + kx];

    float* out = g_i + tb * (COUT * SPAT) + (y0 + py) * 64 + x0 + px;

#pragma unroll 1
    for (int co = 0; co < COUT; co++) {
        float wl[28];
        float4* wlv = (float4*)wl;
        const float4* wv = (const float4*)(ws + co * 28);
#pragma unroll
        for (int q = 0; q < 7; q++) wlv[q] = wv[q];

        float a0 = 0.f, a1 = 0.f, a2 = 0.f;
#pragma unroll
        for (int j = 0; j < 9; j++) {
            a0 = fmaf(r[j],      wl[j],      a0);
            a1 = fmaf(r[j + 9],  wl[j + 9],  a1);
            a2 = fmaf(r[j + 18], wl[j + 18], a2);
        }
        float acc = (a0 + a1) + a2;
        out[co * SPAT] = acc;

        unsigned u   = __float_as_uint(acc);
        unsigned key = ((int)u < 0) ? ~u : (u | 0x80000000u);   // order-preserving encode
        key = __reduce_max_sync(0xffffffffu, key);              // warp max, 1 REDUX
        if (threadIdx.x == 0) atomicMax(&smax[co], key);        // 1 lane -> cheap ATOMS
    }
    __syncthreads();
    if (tid < COUT) atomicMax(&g_thr_keys[t * COUT + tid], smax[tid]);
}

// ---------------------------------------------------------------------------
__global__ void finalize_thr() {
    int i = blockIdx.x * blockDim.x + threadIdx.x;
    if (i < N_THR) {
        unsigned k = g_thr_keys[i];
        unsigned u = (k & 0x80000000u) ? (k & 0x7FFFFFFFu) : ~k;
        float thr  = __uint_as_float(u) + 1e-4f;
        g_thrv[i]  = make_float4(thr, 0.4f * thr, 8.0f / thr, INH * thr);
    }
}

// ---------------------------------------------------------------------------
// LIF + ASF + WTA + inhibition. Block = 32 pixels (x) * 32 channel-threads (y),
// each thread owns channels cy and cy+32. mem lives in registers across all t.
__global__ void __launch_bounds__(1024) lif_kernel(float* __restrict__ out) {
    __shared__ float ssc[32][33];
    __shared__ int   sid[32][33];

    const int p   = threadIdx.x;
    const int cy  = threadIdx.y;
    const int pid = blockIdx.x * 32 + p;
    const int b   = pid >> 12;
    const int sp  = pid & 4095;
    const int c0  = cy, c1 = cy + 32;

    float mem0 = 0.f, mem1 = 0.f;

    for (int t = 0; t < T_STEPS; t++) {
        const int o0 = ((t * B_SZ + b) * COUT + c0) * SPAT + sp;
        const int o1 = o0 + 32 * SPAT;
        const float i0 = g_i[o0];
        const float i1 = g_i[o1];
        const float4 tv0 = g_thrv[t * COUT + c0];
        const float4 tv1 = g_thrv[t * COUT + c1];

        // ASF: thr * sigmoid((max(i,0) - 0.4*thr) * (8/thr))
        float z0 = (fmaxf(i0, 0.f) - tv0.y) * tv0.z;
        float z1 = (fmaxf(i1, 0.f) - tv1.y) * tv1.z;
        float asf0 = tv0.x / (1.f + expf(-z0));
        float asf1 = tv1.x / (1.f + expf(-z1));

        mem0 = fmaf(mem0, DECAY, asf0);
        mem1 = fmaf(mem1, DECAY, asf1);

        float s0 = mem0 > tv0.x ? 1.f : 0.f;
        float s1 = mem1 > tv1.x ? 1.f : 0.f;
        float sc0 = mem0 * s0, sc1 = mem1 * s1;

        // per-thread candidate: smaller channel wins ties (argmax-first semantics)
        float csc; int cid;
        if (sc0 >= sc1) { csc = sc0; cid = (c0 << 1) | (int)s0; }
        else            { csc = sc1; cid = (c1 << 1) | (int)s1; }
        ssc[cy][p] = csc; sid[cy][p] = cid;
        __syncthreads();
#pragma unroll
        for (int off = 16; off >= 1; off >>= 1) {
            if (cy < off) {
                float a  = ssc[cy][p],      bb = ssc[cy + off][p];
                int   ia = sid[cy][p],      ib = sid[cy + off][p];
                if (bb > a || (bb == a && (ib >> 1) < (ia >> 1))) {
                    ssc[cy][p] = bb; sid[cy][p] = ib;
                }
            }
            __syncthreads();
        }
        const int wz = sid[0][p];
        __syncthreads();   // all reads of slot 0 done before next t's stores

        const int   wc  = wz >> 1;
        const float any = (float)(wz & 1);        // winner's spike -> any_sp
        float sn0 = (wc == c0) ? s0 : 0.f;
        float sn1 = (wc == c1) ? s1 : 0.f;

        // reset fired neuron; inhibit non-winners at spiking locations
        mem0 = (sn0 > 0.f) ? 0.f : mem0 - tv0.w * any;
        mem1 = (sn1 > 0.f) ? 0.f : mem1 - tv1.w * any;

        out[o0] = sn0;
        out[o1] = sn1;
    }
}

// ---------------------------------------------------------------------------
extern "C" void kernel_launch(void* const* d_in, const int* in_sizes, int n_in,
                              void* d_out, int out_size) {
    const float* x = (const float*)d_in[0];
    const float* W = (const float*)d_in[1];
    if (n_in >= 2 && in_sizes[0] == COUT * CIN * 9) {  // defensive order swap
        const float* tmp = x; x = W; W = tmp;
    }

    init_keys<<<1, N_THR>>>();

    dim3 cb(32, 8);
    dim3 cg(2, 8, T_STEPS * B_SZ);
    conv_kernel<<<cg, cb>>>(x, W);

    finalize_thr<<<1, N_THR>>>();

    lif_kernel<<<(B_SZ * SPAT) / 32, dim3(32, 32)>>>((float*)d_out);
}